// round 13
// baseline (speedup 1.0000x reference)
#include <cuda_runtime.h>
#include <cuda_bf16.h>
#include <stdint.h>
#include <math.h>

#define B_  64
#define T_  512
#define E_  512
#define H_  256
#define NT_ 20
#define HBUF (16 * 264 * 2)   /* bytes per h buffer */

// ---------------- scratch (device globals) ------------------------------------
__device__ __nv_bfloat16 g_xbfA[B_ * T_ * E_];        // 32 MB  layer-0 input (bf16)
__device__ __nv_bfloat16 g_xbfB[B_ * T_ * E_];        // 32 MB  layer-1 input (bf16)
__device__ float g_xA[B_ * T_ * E_];                  // 64 MB  final layer output (fp32)
__device__ float g_xg[(size_t)B_ * T_ * 2048];        // 256 MB input projections
__device__ __nv_bfloat16 g_wbf[2 * 2048 * E_];        // 4 MB   w_ih in bf16
__device__ float g_em[B_ * T_ * NT_];
__device__ float g_llh[B_];

// ---------------- small helpers ------------------------------------------------
__device__ __forceinline__ unsigned pack_bf2(float a, float b) {
    __nv_bfloat162 h2 = __floats2bfloat162_rn(a, b);
    return *reinterpret_cast<unsigned*>(&h2);
}
__device__ __forceinline__ void ldsm4(unsigned& a0, unsigned& a1, unsigned& a2, unsigned& a3,
                                      unsigned addr) {
    asm volatile("ldmatrix.sync.aligned.m8n8.x4.shared.b16 {%0,%1,%2,%3}, [%4];\n"
                 : "=r"(a0), "=r"(a1), "=r"(a2), "=r"(a3) : "r"(addr));
}
__device__ __forceinline__ void mma_bf(float& d0, float& d1, float& d2, float& d3,
                                       unsigned a0, unsigned a1, unsigned a2, unsigned a3,
                                       unsigned b0, unsigned b1) {
    asm volatile("mma.sync.aligned.m16n8k16.row.col.f32.bf16.bf16.f32 "
                 "{%0,%1,%2,%3},{%4,%5,%6,%7},{%8,%9},{%0,%1,%2,%3};\n"
                 : "+f"(d0), "+f"(d1), "+f"(d2), "+f"(d3)
                 : "r"(a0), "r"(a1), "r"(a2), "r"(a3), "r"(b0), "r"(b1));
}
__device__ __forceinline__ unsigned mapa_u32(unsigned addr, int rank) {
    unsigned out;
    asm("mapa.shared::cluster.u32 %0, %1, %2;" : "=r"(out) : "r"(addr), "r"(rank));
    return out;
}
__device__ __forceinline__ void st_dsm64(unsigned addr, unsigned long long v) {
    asm volatile("st.shared::cluster.b64 [%0], %1;" :: "r"(addr), "l"(v) : "memory");
}
__device__ __forceinline__ void st_dsm32_release(unsigned addr, unsigned v) {
    asm volatile("st.release.cluster.shared::cluster.b32 [%0], %1;"
                 :: "r"(addr), "r"(v) : "memory");
}
__device__ __forceinline__ unsigned ld_acq_local(unsigned addr) {
    unsigned v;
    asm volatile("ld.acquire.cluster.shared::cta.b32 %0, [%1];"
                 : "=r"(v) : "r"(addr) : "memory");
    return v;
}
__device__ __forceinline__ float tanhfast(float x) {
    float y;
    asm("tanh.approx.f32 %0, %1;" : "=f"(y) : "f"(x));
    return y;
}
__device__ __forceinline__ float sigm(float x) { return 0.5f * tanhfast(0.5f * x) + 0.5f; }

// ---------------- conversion / gather ------------------------------------------
__global__ void k_wcvt(const float* __restrict__ w_ih) {
    int i = (blockIdx.x * 256 + threadIdx.x) * 4;
    float4 v = *(const float4*)(w_ih + i);
    uint2 o;
    o.x = pack_bf2(v.x, v.y);
    o.y = pack_bf2(v.z, v.w);
    *(uint2*)(g_wbf + i) = o;
}

__global__ void k_gather(const int* __restrict__ ids, const float* __restrict__ embed) {
    int bt = blockIdx.x;
    int id = ids[bt];
    int e = threadIdx.x * 4;
    float4 v = *(const float4*)(embed + (size_t)id * E_ + e);
    uint2 o;
    o.x = pack_bf2(v.x, v.y);
    o.y = pack_bf2(v.z, v.w);
    *(uint2*)(g_xbfA + (size_t)bt * E_ + e) = o;
}

// ---------------- bf16 tensor-core GEMM: xg = X @ W^T + bias -------------------
__global__ void __launch_bounds__(256) k_gemm_bf(const float* __restrict__ b_ih,
                                                 const float* __restrict__ b_hh,
                                                 int layer) {
    __shared__ __align__(16) __nv_bfloat16 As[128 * 40];
    __shared__ __align__(16) __nv_bfloat16 Bs[128 * 40];

    const __nv_bfloat16* Xbf = layer ? g_xbfB : g_xbfA;
    const __nv_bfloat16* Wbf = g_wbf + (size_t)layer * 2048 * E_;
    const float* bi = b_ih + layer * 2048;
    const float* bh = b_hh + layer * 2048;

    int m0 = blockIdx.y * 128, n0 = blockIdx.x * 128;
    int tid = threadIdx.x, w = tid >> 5, lane = tid & 31;

    const __nv_bfloat16* Ag = Xbf + (size_t)(m0 + (tid >> 2)) * E_ + (tid & 3) * 8;
    const __nv_bfloat16* Bg = Wbf + (size_t)(n0 + (tid >> 2)) * E_ + (tid & 3) * 8;
    int soff = (tid >> 2) * 40 + (tid & 3) * 8;

    unsigned a_base = (unsigned)__cvta_generic_to_shared(As);
    unsigned b_base = (unsigned)__cvta_generic_to_shared(Bs);

    int mbase = (w & 1) * 64, nbase = (w >> 1) * 32;

    float acc[4][4][4];
#pragma unroll
    for (int i = 0; i < 4; i++)
#pragma unroll
        for (int j = 0; j < 4; j++)
#pragma unroll
            for (int r = 0; r < 4; r++) acc[i][j][r] = 0.f;

    uint4 ra[2], rb[2];
#pragma unroll
    for (int i = 0; i < 2; i++) {
        ra[i] = *(const uint4*)(Ag + i * 64 * E_);
        rb[i] = *(const uint4*)(Bg + i * 64 * E_);
    }

    for (int kb = 0; kb < 16; ++kb) {
#pragma unroll
        for (int i = 0; i < 2; i++) {
            *(uint4*)&As[soff + i * 64 * 40] = ra[i];
            *(uint4*)&Bs[soff + i * 64 * 40] = rb[i];
        }
        __syncthreads();
        if (kb < 15) {
#pragma unroll
            for (int i = 0; i < 2; i++) {
                ra[i] = *(const uint4*)(Ag + (kb + 1) * 32 + i * 64 * E_);
                rb[i] = *(const uint4*)(Bg + (kb + 1) * 32 + i * 64 * E_);
            }
        }
#pragma unroll
        for (int kk = 0; kk < 32; kk += 16) {
            unsigned aF[4][4], bF[4][2];
#pragma unroll
            for (int mt = 0; mt < 4; ++mt) {
                int row = mbase + mt * 16 + (lane & 15);
                int col = kk + ((lane >> 4) << 3);
                ldsm4(aF[mt][0], aF[mt][1], aF[mt][2], aF[mt][3],
                      a_base + (unsigned)(row * 40 + col) * 2);
            }
#pragma unroll
            for (int p = 0; p < 2; ++p) {
                int row = nbase + 16 * p + ((lane >> 4) << 3) + (lane & 7);
                int colb = kk + (((lane >> 3) & 1) << 3);
                ldsm4(bF[2 * p][0], bF[2 * p][1], bF[2 * p + 1][0], bF[2 * p + 1][1],
                      b_base + (unsigned)(row * 40 + colb) * 2);
            }
#pragma unroll
            for (int mt = 0; mt < 4; ++mt)
#pragma unroll
                for (int nt = 0; nt < 4; ++nt)
                    mma_bf(acc[mt][nt][0], acc[mt][nt][1], acc[mt][nt][2], acc[mt][nt][3],
                           aF[mt][0], aF[mt][1], aF[mt][2], aF[mt][3],
                           bF[nt][0], bF[nt][1]);
        }
        __syncthreads();
    }

#pragma unroll
    for (int nt = 0; nt < 4; ++nt) {
        int coln = n0 + nbase + 8 * nt + 2 * (lane & 3);
        float bb0 = bi[coln] + bh[coln];
        float bb1 = bi[coln + 1] + bh[coln + 1];
#pragma unroll
        for (int mt = 0; mt < 4; ++mt) {
            int row = m0 + mbase + 16 * mt + (lane >> 2);
            *(float2*)&g_xg[(size_t)row * 2048 + coln] =
                make_float2(acc[mt][nt][0] + bb0, acc[mt][nt][1] + bb1);
            *(float2*)&g_xg[(size_t)(row + 8) * 2048 + coln] =
                make_float2(acc[mt][nt][2] + bb0, acc[mt][nt][3] + bb1);
        }
    }
}

// ---------------- persistent BiLSTM layer: barrier-free flag exchange ----------
// Round-8 partition: 64 CTAs = 8 clusters of 8; cluster = (dir, batch-block 16);
// CTA rank ub owns units [ub*32,ub*32+32); warp w owns units 4w..4w+3 x 4 gates.
// Exchange: TRIPLE-buffered h; each producing lane pushes 4x8B data to its fixed
// peer then one st.release flag (value s+1).  Consumers spin on 256 LOCAL flag
// words (ld.acquire) then __syncthreads.  No cluster barrier in the loop.
// Safety: producer <= slowest consumer + 1 step (data dependency), so buffer
// (s+1)%3 never collides with in-flight readers of (s-1)%3 / s%3.
__global__ void __launch_bounds__(256, 1) __cluster_dims__(8, 1, 1)
k_lstm(const float* __restrict__ w_hh, const int* __restrict__ lengths,
       int layer, int out_fp32) {
    __shared__ __align__(16) __nv_bfloat16 h_shT[3][16 * 264]; // triple-buffered h
    __shared__ __align__(16) unsigned long long h_own[8][16];  // [warp][batch]
    __shared__ __align__(16) unsigned flags[3][256];           // [buf][256 producer lanes]
    __shared__ int len_sh[16];

    int cta = blockIdx.x;
    int ub  = cta & 7;          // cluster rank
    int grp = cta >> 3;
    int bb  = grp & 3;
    int dir = grp >> 2;
    int tid = threadIdx.x;
    int w = tid >> 5, lane = tid & 31;

    // ---- B fragments: warp w's 16 columns = units {4w..4w+3} x gates {0..3} ----
    unsigned bfr[16][2][2];
    {
        int c2 = (lane & 3) * 2;
#pragma unroll
        for (int p = 0; p < 2; ++p) {
            int lc = 8 * p + (lane >> 2);
            int g = lc & 3, du = lc >> 2;
            const float* wr = w_hh +
                ((size_t)((layer * 2 + dir) * 1024 + g * 256 + ub * 32 + w * 4 + du)) * 256;
#pragma unroll
            for (int kt = 0; kt < 16; ++kt) {
                bfr[kt][p][0] = pack_bf2(wr[kt * 16 + c2],     wr[kt * 16 + c2 + 1]);
                bfr[kt][p][1] = pack_bf2(wr[kt * 16 + c2 + 8], wr[kt * 16 + c2 + 9]);
            }
        }
    }
    if (tid < 16) len_sh[tid] = lengths[bb * 16 + tid];
    // zero h buffer 0 (step-0 h state) and all flags
    for (int i = tid; i < 16 * 264 / 2; i += 256)
        ((unsigned*)h_shT[0])[i] = 0u;
#pragma unroll
    for (int b = 0; b < 3; ++b) flags[b][tid] = 0u;
    __syncthreads();
    asm volatile("barrier.cluster.arrive.aligned;" ::: "memory");
    asm volatile("barrier.cluster.wait.aligned;" ::: "memory");

    int maxlen = 0;
#pragma unroll
    for (int i = 0; i < 16; i++) maxlen = max(maxlen, len_sh[i]);

    // gate mapping: thread (w, lane) -> batches r, r+8 ; unit 4w + du
    int q = lane & 3, r = lane >> 2;
    bool qe = (q & 1) == 0;
    int du = ((q & 1) << 1) | (q >> 1);
    int unit = ub * 32 + 4 * w + du;
    int len0 = len_sh[r], len1 = len_sh[r + 8];
    int gb0 = bb * 16 + r, gb1 = bb * 16 + r + 8;
    const float* xg0p = g_xg + (size_t)gb0 * T_ * 2048 + dir * 1024 + unit;
    const float* xg1p = g_xg + (size_t)gb1 * T_ * 2048 + dir * 1024 + unit;

    unsigned hsh_base = (unsigned)__cvta_generic_to_shared(&h_shT[0][0]);
    unsigned flg_base = (unsigned)__cvta_generic_to_shared(&flags[0][0]);
    unsigned a_addr0 = hsh_base + (unsigned)(lane & 15) * 528 + ((lane >> 4) << 4);

    // push mapping: lane's FIXED peer = lane&7; batches (lane>>3)+{0,4,8,12}
    int peer = lane & 7;
    unsigned dsm_peer = mapa_u32(hsh_base + (unsigned)((ub * 32 + 4 * w) * 2), peer);
    // flag word identity at the peer: (src_rank=ub, warp=w, lane>>3)
    unsigned flg_peer = mapa_u32(flg_base, peer)
                      + (unsigned)((ub * 32 + w * 4 + (lane >> 3)) * 4);
    // local flag this thread polls
    unsigned flg_local = flg_base + (unsigned)(tid * 4);

    float cst0 = 0.f, cst1 = 0.f;
    float xa[2][8];

    // prefetch xg for s = 0
    {
        int pos0 = dir ? (len0 - 1) : 0;
        int pos1 = dir ? (len1 - 1) : 0;
        const float* p0 = xg0p + (size_t)pos0 * 2048;
        const float* p1 = xg1p + (size_t)pos1 * 2048;
        xa[0][0] = p0[0]; xa[0][1] = p0[256]; xa[0][2] = p0[512]; xa[0][3] = p0[768];
        xa[0][4] = p1[0]; xa[0][5] = p1[256]; xa[0][6] = p1[512]; xa[0][7] = p1[768];
    }

    for (int s = 0; s < maxlen; ++s) {
        int pb = s & 1;           // xa buffer parity
        int hb = s % 3;           // h buffer index
        // ---- prefetch xg for s+1 (issues before the flag wait) ----
        if (s + 1 < maxlen) {
            int sn = s + 1;
            if (sn < len0) {
                int pos0 = dir ? (len0 - 1 - sn) : sn;
                const float* pp = xg0p + (size_t)pos0 * 2048;
                xa[pb ^ 1][0] = pp[0]; xa[pb ^ 1][1] = pp[256];
                xa[pb ^ 1][2] = pp[512]; xa[pb ^ 1][3] = pp[768];
            }
            if (sn < len1) {
                int pos1 = dir ? (len1 - 1 - sn) : sn;
                const float* pp = xg1p + (size_t)pos1 * 2048;
                xa[pb ^ 1][4] = pp[0]; xa[pb ^ 1][5] = pp[256];
                xa[pb ^ 1][6] = pp[512]; xa[pb ^ 1][7] = pp[768];
            }
        }

        // ---- wait: all 256 producer-lane flags for buffer hb == s ----
        if (s > 0) {
            unsigned fa = flg_local + (unsigned)(hb * 1024);
            while (ld_acq_local(fa) != (unsigned)s) { }
            __syncthreads();
        }

        // ---- recurrent mma on h_shT[hb], split even/odd chains ----
        unsigned a_addr = a_addr0 + (unsigned)hb * HBUF;
        float aA[2][4], aB[2][4];
#pragma unroll
        for (int t = 0; t < 2; ++t)
#pragma unroll
            for (int i = 0; i < 4; ++i) { aA[t][i] = 0.f; aB[t][i] = 0.f; }
#pragma unroll
        for (int kt = 0; kt < 16; kt += 2) {
            unsigned A0, A1, A2, A3;
            ldsm4(A0, A1, A2, A3, a_addr + kt * 32);
            mma_bf(aA[0][0], aA[0][1], aA[0][2], aA[0][3],
                   A0, A1, A2, A3, bfr[kt][0][0], bfr[kt][0][1]);
            mma_bf(aA[1][0], aA[1][1], aA[1][2], aA[1][3],
                   A0, A1, A2, A3, bfr[kt][1][0], bfr[kt][1][1]);
            unsigned B0, B1, B2, B3;
            ldsm4(B0, B1, B2, B3, a_addr + (kt + 1) * 32);
            mma_bf(aB[0][0], aB[0][1], aB[0][2], aB[0][3],
                   B0, B1, B2, B3, bfr[kt + 1][0][0], bfr[kt + 1][0][1]);
            mma_bf(aB[1][0], aB[1][1], aB[1][2], aB[1][3],
                   B0, B1, B2, B3, bfr[kt + 1][1][0], bfr[kt + 1][1][1]);
        }
        float acc0[4], acc1[4];
#pragma unroll
        for (int i = 0; i < 4; ++i) { acc0[i] = aA[0][i] + aB[0][i];
                                      acc1[i] = aA[1][i] + aB[1][i]; }

        // ---- lane-pair exchange: swap the "other" ntile with partner ----
        float own[4], rcv[4];
#pragma unroll
        for (int i = 0; i < 4; ++i) {
            float snd = qe ? acc1[i] : acc0[i];
            rcv[i] = __shfl_xor_sync(0xFFFFFFFFu, snd, 1);
            own[i] = qe ? acc0[i] : acc1[i];
        }
        float ai0 = (qe ? own[0] : rcv[0]) + xa[pb][0];
        float af0 = (qe ? own[1] : rcv[1]) + xa[pb][1];
        float ag0 = (qe ? rcv[0] : own[0]) + xa[pb][2];
        float ao0 = (qe ? rcv[1] : own[1]) + xa[pb][3];
        float ai1 = (qe ? own[2] : rcv[2]) + xa[pb][4];
        float af1 = (qe ? own[3] : rcv[3]) + xa[pb][5];
        float ag1 = (qe ? rcv[2] : own[2]) + xa[pb][6];
        float ao1 = (qe ? rcv[3] : own[3]) + xa[pb][7];

        bool v0 = s < len0, v1 = s < len1;
        float hv0 = 0.f, hv1 = 0.f;
        if (v0) {
            cst0 = sigm(af0) * cst0 + sigm(ai0) * tanhfast(ag0);
            hv0 = sigm(ao0) * tanhfast(cst0);
            ((__nv_bfloat16*)&h_own[w][r])[du] = __float2bfloat16(hv0);
        }
        if (v1) {
            cst1 = sigm(af1) * cst1 + sigm(ai1) * tanhfast(ag1);
            hv1 = sigm(ao1) * tanhfast(cst1);
            ((__nv_bfloat16*)&h_own[w][r + 8])[du] = __float2bfloat16(hv1);
        }
        __syncwarp();

        // ---- push own slice to fixed peer, then release-flag (value s+1) ----
        if (s + 1 < maxlen) {
            int hn = (s + 1) % 3;
            unsigned dbase = dsm_peer + (unsigned)hn * HBUF;
#pragma unroll
            for (int j = 0; j < 4; ++j) {
                int batch = (lane >> 3) + 4 * j;
                st_dsm64(dbase + (unsigned)batch * 528, h_own[w][batch]);
            }
            st_dsm32_release(flg_peer + (unsigned)(hn * 1024), (unsigned)(s + 1));
        }

        // ---- off critical path: write layer output ----
        if (v0) {
            int pos0 = dir ? (len0 - 1 - s) : s;
            size_t xoff = ((size_t)gb0 * T_ + pos0) * E_ + dir * H_ + unit;
            if (out_fp32) g_xA[xoff] = hv0; else g_xbfB[xoff] = __float2bfloat16(hv0);
        }
        if (v1) {
            int pos1 = dir ? (len1 - 1 - s) : s;
            size_t xoff = ((size_t)gb1 * T_ + pos1) * E_ + dir * H_ + unit;
            if (out_fp32) g_xA[xoff] = hv1; else g_xbfB[xoff] = __float2bfloat16(hv1);
        }
    }

    // ---- fused tail zeroing: positions t in [len, T) get zeros ----
    for (int t = len0; t < T_; ++t) {
        size_t xoff = ((size_t)gb0 * T_ + t) * E_ + dir * H_ + unit;
        if (out_fp32) g_xA[xoff] = 0.f; else g_xbfB[xoff] = __float2bfloat16(0.f);
    }
    for (int t = len1; t < T_; ++t) {
        size_t xoff = ((size_t)gb1 * T_ + t) * E_ + dir * H_ + unit;
        if (out_fp32) g_xA[xoff] = 0.f; else g_xbfB[xoff] = __float2bfloat16(0.f);
    }

    // final barrier: cover in-flight remote ops before any CTA exits
    asm volatile("barrier.cluster.arrive.aligned;" ::: "memory");
    asm volatile("barrier.cluster.wait.aligned;" ::: "memory");
}

// ---------------- emissions -----------------------------------------------------
__global__ void k_emis(const float* __restrict__ fc_w, const float* __restrict__ fc_b) {
    int w = blockIdx.x * 8 + (threadIdx.x >> 5);
    int lane = threadIdx.x & 31;
    int j = lane < NT_ ? lane : 0;
    const float* x = g_xA + (size_t)w * E_;
    float acc = fc_b[j];
#pragma unroll 4
    for (int k = 0; k < E_; k += 4) {
        float4 xv = *(const float4*)(x + k);
        acc += xv.x * fc_w[(k + 0) * NT_ + j] + xv.y * fc_w[(k + 1) * NT_ + j]
             + xv.z * fc_w[(k + 2) * NT_ + j] + xv.w * fc_w[(k + 3) * NT_ + j];
    }
    if (lane < NT_) g_em[(size_t)w * NT_ + lane] = acc;
}

// ---------------- CRF -----------------------------------------------------------
__global__ void k_crf(const int* __restrict__ tags, const int* __restrict__ lengths,
                      const float* __restrict__ crf_start, const float* __restrict__ crf_end,
                      const float* __restrict__ crf_trans) {
    int b = blockIdx.x;
    int lane = threadIdx.x;
    int len = lengths[b];
    const int* tg = tags + b * T_;
    const float* em = g_em + (size_t)b * T_ * NT_;

    float part = 0.f;
    for (int t = lane; t < T_; t += 32) {
        if (t < len) {
            int tt = tg[t];
            part += em[t * NT_ + tt];
            if (t >= 1) part += crf_trans[tg[t - 1] * NT_ + tt];
        }
    }
#pragma unroll
    for (int o = 16; o; o >>= 1) part += __shfl_xor_sync(0xFFFFFFFFu, part, o);
    float numer = part + crf_start[tg[0]] + crf_end[tg[len - 1]];

    int j = lane < NT_ ? lane : 0;
    float etr[NT_];
#pragma unroll
    for (int i = 0; i < NT_; i++) etr[i] = expf(crf_trans[i * NT_ + j]);

    float s = crf_start[j] + em[j];
    for (int t = 1; t < len; ++t) {
        float sl = (lane < NT_) ? s : -1e30f;
        float m = sl;
#pragma unroll
        for (int o = 16; o; o >>= 1) m = fmaxf(m, __shfl_xor_sync(0xFFFFFFFFu, m, o));
        float es = expf(s - m);
        float z = 0.f;
#pragma unroll
        for (int i = 0; i < NT_; i++) {
            float ei = __shfl_sync(0xFFFFFFFFu, es, i);
            z += ei * etr[i];
        }
        s = m + logf(z) + em[t * NT_ + j];
    }
    s += crf_end[j];
    float sj = (lane < NT_) ? s : -1e30f;
    float mm = sj;
#pragma unroll
    for (int o = 16; o; o >>= 1) mm = fmaxf(mm, __shfl_xor_sync(0xFFFFFFFFu, mm, o));
    float zz = (lane < NT_) ? expf(sj - mm) : 0.f;
#pragma unroll
    for (int o = 16; o; o >>= 1) zz += __shfl_xor_sync(0xFFFFFFFFu, zz, o);
    float logZ = mm + logf(zz);
    if (lane == 0) g_llh[b] = numer - logZ;
}

// ---------------- final reduction ----------------------------------------------
__global__ void k_reduce(float* __restrict__ out) {
    int lane = threadIdx.x;
    float v = g_llh[lane];
    __shared__ float tmp[2];
#pragma unroll
    for (int o = 16; o; o >>= 1) v += __shfl_xor_sync(0xFFFFFFFFu, v, o);
    if ((lane & 31) == 0) tmp[lane >> 5] = v;
    __syncthreads();
    if (lane == 0) out[0] = -(tmp[0] + tmp[1]);
}

// ---------------- host launcher -------------------------------------------------
extern "C" void kernel_launch(void* const* d_in, const int* in_sizes, int n_in,
                              void* d_out, int out_size) {
    const int*   ids   = (const int*)d_in[0];
    const int*   lens  = (const int*)d_in[1];
    const int*   tags  = (const int*)d_in[2];
    const float* embed = (const float*)d_in[3];
    const float* w_ih  = (const float*)d_in[4];
    const float* w_hh  = (const float*)d_in[5];
    const float* b_ih  = (const float*)d_in[6];
    const float* b_hh  = (const float*)d_in[7];
    const float* fc_w  = (const float*)d_in[8];
    const float* fc_b  = (const float*)d_in[9];
    const float* c_st  = (const float*)d_in[10];
    const float* c_en  = (const float*)d_in[11];
    const float* c_tr  = (const float*)d_in[12];
    float* out = (float*)d_out;

    k_wcvt<<<2048, 256>>>(w_ih);                       // 0
    k_gather<<<B_ * T_, 128>>>(ids, embed);            // 1
    k_gemm_bf<<<dim3(16, 256), 256>>>(b_ih, b_hh, 0);  // 2
    k_lstm<<<64, 256>>>(w_hh, lens, 0, 0);             // 3
    k_gemm_bf<<<dim3(16, 256), 256>>>(b_ih, b_hh, 1);  // 4
    k_lstm<<<64, 256>>>(w_hh, lens, 1, 1);             // 5  <- profiled
    k_emis<<<B_ * T_ / 8, 256>>>(fc_w, fc_b);          // 6
    k_crf<<<B_, 32>>>(tags, lens, c_st, c_en, c_tr);   // 7
    k_reduce<<<1, 64>>>(out);                          // 8
}

// round 14
// speedup vs baseline: 1.0366x; 1.0366x over previous
#include <cuda_runtime.h>
#include <cuda_bf16.h>
#include <stdint.h>
#include <math.h>

#define B_  64
#define T_  512
#define E_  512
#define H_  256
#define NT_ 20
#define HBUF (16 * 264 * 2)   /* bytes per h buffer */

// ---------------- scratch (device globals) ------------------------------------
__device__ __nv_bfloat16 g_xbfA[B_ * T_ * E_];        // 32 MB  layer-0 input (bf16)
__device__ __nv_bfloat16 g_xbfB[B_ * T_ * E_];        // 32 MB  layer-1 input (bf16)
__device__ float g_xA[B_ * T_ * E_];                  // 64 MB  final layer output (fp32)
__device__ float g_xg[(size_t)B_ * T_ * 2048];        // 256 MB input projections
__device__ __nv_bfloat16 g_wbf[2 * 2048 * E_];        // 4 MB   w_ih in bf16
__device__ float g_em[B_ * T_ * NT_];
__device__ float g_llh[B_];

// ---------------- small helpers ------------------------------------------------
__device__ __forceinline__ unsigned pack_bf2(float a, float b) {
    __nv_bfloat162 h2 = __floats2bfloat162_rn(a, b);
    return *reinterpret_cast<unsigned*>(&h2);
}
__device__ __forceinline__ void ldsm4(unsigned& a0, unsigned& a1, unsigned& a2, unsigned& a3,
                                      unsigned addr) {
    asm volatile("ldmatrix.sync.aligned.m8n8.x4.shared.b16 {%0,%1,%2,%3}, [%4];\n"
                 : "=r"(a0), "=r"(a1), "=r"(a2), "=r"(a3) : "r"(addr));
}
__device__ __forceinline__ void mma_bf(float& d0, float& d1, float& d2, float& d3,
                                       unsigned a0, unsigned a1, unsigned a2, unsigned a3,
                                       unsigned b0, unsigned b1) {
    asm volatile("mma.sync.aligned.m16n8k16.row.col.f32.bf16.bf16.f32 "
                 "{%0,%1,%2,%3},{%4,%5,%6,%7},{%8,%9},{%0,%1,%2,%3};\n"
                 : "+f"(d0), "+f"(d1), "+f"(d2), "+f"(d3)
                 : "r"(a0), "r"(a1), "r"(a2), "r"(a3), "r"(b0), "r"(b1));
}
__device__ __forceinline__ unsigned mapa_u32(unsigned addr, int rank) {
    unsigned out;
    asm("mapa.shared::cluster.u32 %0, %1, %2;" : "=r"(out) : "r"(addr), "r"(rank));
    return out;
}
__device__ __forceinline__ void st_dsm64(unsigned addr, unsigned long long v) {
    asm volatile("st.shared::cluster.b64 [%0], %1;" :: "r"(addr), "l"(v) : "memory");
}
__device__ __forceinline__ float tanhfast(float x) {
    float y;
    asm("tanh.approx.f32 %0, %1;" : "=f"(y) : "f"(x));
    return y;
}
__device__ __forceinline__ float sigm(float x) { return 0.5f * tanhfast(0.5f * x) + 0.5f; }

// ---------------- conversion / gather ------------------------------------------
__global__ void k_wcvt(const float* __restrict__ w_ih) {
    int i = (blockIdx.x * 256 + threadIdx.x) * 4;
    float4 v = *(const float4*)(w_ih + i);
    uint2 o;
    o.x = pack_bf2(v.x, v.y);
    o.y = pack_bf2(v.z, v.w);
    *(uint2*)(g_wbf + i) = o;
}

__global__ void k_gather(const int* __restrict__ ids, const float* __restrict__ embed) {
    int bt = blockIdx.x;
    int id = ids[bt];
    int e = threadIdx.x * 4;
    float4 v = *(const float4*)(embed + (size_t)id * E_ + e);
    uint2 o;
    o.x = pack_bf2(v.x, v.y);
    o.y = pack_bf2(v.z, v.w);
    *(uint2*)(g_xbfA + (size_t)bt * E_ + e) = o;
}

// ---------------- bf16 tensor-core GEMM: xg = X @ W^T + bias -------------------
__global__ void __launch_bounds__(256) k_gemm_bf(const float* __restrict__ b_ih,
                                                 const float* __restrict__ b_hh,
                                                 int layer) {
    __shared__ __align__(16) __nv_bfloat16 As[128 * 40];
    __shared__ __align__(16) __nv_bfloat16 Bs[128 * 40];

    const __nv_bfloat16* Xbf = layer ? g_xbfB : g_xbfA;
    const __nv_bfloat16* Wbf = g_wbf + (size_t)layer * 2048 * E_;
    const float* bi = b_ih + layer * 2048;
    const float* bh = b_hh + layer * 2048;

    int m0 = blockIdx.y * 128, n0 = blockIdx.x * 128;
    int tid = threadIdx.x, w = tid >> 5, lane = tid & 31;

    const __nv_bfloat16* Ag = Xbf + (size_t)(m0 + (tid >> 2)) * E_ + (tid & 3) * 8;
    const __nv_bfloat16* Bg = Wbf + (size_t)(n0 + (tid >> 2)) * E_ + (tid & 3) * 8;
    int soff = (tid >> 2) * 40 + (tid & 3) * 8;

    unsigned a_base = (unsigned)__cvta_generic_to_shared(As);
    unsigned b_base = (unsigned)__cvta_generic_to_shared(Bs);

    int mbase = (w & 1) * 64, nbase = (w >> 1) * 32;

    float acc[4][4][4];
#pragma unroll
    for (int i = 0; i < 4; i++)
#pragma unroll
        for (int j = 0; j < 4; j++)
#pragma unroll
            for (int r = 0; r < 4; r++) acc[i][j][r] = 0.f;

    uint4 ra[2], rb[2];
#pragma unroll
    for (int i = 0; i < 2; i++) {
        ra[i] = *(const uint4*)(Ag + i * 64 * E_);
        rb[i] = *(const uint4*)(Bg + i * 64 * E_);
    }

    for (int kb = 0; kb < 16; ++kb) {
#pragma unroll
        for (int i = 0; i < 2; i++) {
            *(uint4*)&As[soff + i * 64 * 40] = ra[i];
            *(uint4*)&Bs[soff + i * 64 * 40] = rb[i];
        }
        __syncthreads();
        if (kb < 15) {
#pragma unroll
            for (int i = 0; i < 2; i++) {
                ra[i] = *(const uint4*)(Ag + (kb + 1) * 32 + i * 64 * E_);
                rb[i] = *(const uint4*)(Bg + (kb + 1) * 32 + i * 64 * E_);
            }
        }
#pragma unroll
        for (int kk = 0; kk < 32; kk += 16) {
            unsigned aF[4][4], bF[4][2];
#pragma unroll
            for (int mt = 0; mt < 4; ++mt) {
                int row = mbase + mt * 16 + (lane & 15);
                int col = kk + ((lane >> 4) << 3);
                ldsm4(aF[mt][0], aF[mt][1], aF[mt][2], aF[mt][3],
                      a_base + (unsigned)(row * 40 + col) * 2);
            }
#pragma unroll
            for (int p = 0; p < 2; ++p) {
                int row = nbase + 16 * p + ((lane >> 4) << 3) + (lane & 7);
                int colb = kk + (((lane >> 3) & 1) << 3);
                ldsm4(bF[2 * p][0], bF[2 * p][1], bF[2 * p + 1][0], bF[2 * p + 1][1],
                      b_base + (unsigned)(row * 40 + colb) * 2);
            }
#pragma unroll
            for (int mt = 0; mt < 4; ++mt)
#pragma unroll
                for (int nt = 0; nt < 4; ++nt)
                    mma_bf(acc[mt][nt][0], acc[mt][nt][1], acc[mt][nt][2], acc[mt][nt][3],
                           aF[mt][0], aF[mt][1], aF[mt][2], aF[mt][3],
                           bF[nt][0], bF[nt][1]);
        }
        __syncthreads();
    }

#pragma unroll
    for (int nt = 0; nt < 4; ++nt) {
        int coln = n0 + nbase + 8 * nt + 2 * (lane & 3);
        float bb0 = bi[coln] + bh[coln];
        float bb1 = bi[coln + 1] + bh[coln + 1];
#pragma unroll
        for (int mt = 0; mt < 4; ++mt) {
            int row = m0 + mbase + 16 * mt + (lane >> 2);
            *(float2*)&g_xg[(size_t)row * 2048 + coln] =
                make_float2(acc[mt][nt][0] + bb0, acc[mt][nt][1] + bb1);
            *(float2*)&g_xg[(size_t)(row + 8) * 2048 + coln] =
                make_float2(acc[mt][nt][2] + bb0, acc[mt][nt][3] + bb1);
        }
    }
}

// ---------------- persistent BiLSTM layer: cluster-of-4, 512-thread CTAs -------
// 32 CTAs (512 thr) = 8 clusters of 4.  Cluster = (dir, batch-block of 16).
// CTA rank ub owns units [ub*64, ub*64+64).  16 warps; warp w owns units
// 4w..4w+3 with all four gates in its mma D-fragment — per-warp duty identical
// to the round-8 best (64 weight regs/thread, no spill).  Push to 3 remote
// peers + self via mapa; barrier = cluster.sync over FOUR CTAs (less skew,
// fewer arrivals, shorter drain than the 8-CTA version).
__global__ void __launch_bounds__(512, 1) __cluster_dims__(4, 1, 1)
k_lstm(const float* __restrict__ w_hh, const int* __restrict__ lengths,
       int layer, int out_fp32) {
    __shared__ __align__(16) __nv_bfloat16 h_shD[2][16 * 264]; // dbl-buffered full h
    __shared__ __align__(16) unsigned long long h_own[16][16]; // [warp][batch] 4 units
    __shared__ int len_sh[16];

    int cta = blockIdx.x;
    int ub  = cta & 3;          // cluster rank
    int grp = cta >> 2;
    int bb  = grp & 3;
    int dir = grp >> 2;
    int tid = threadIdx.x;
    int w = tid >> 5, lane = tid & 31;     // w in 0..15

    // ---- B fragments: warp w's 16 columns = units {4w..4w+3} x gates {0..3} ----
    unsigned bfr[16][2][2];
    {
        int c2 = (lane & 3) * 2;
#pragma unroll
        for (int p = 0; p < 2; ++p) {
            int lc = 8 * p + (lane >> 2);
            int g = lc & 3, du = lc >> 2;
            const float* wr = w_hh +
                ((size_t)((layer * 2 + dir) * 1024 + g * 256 + ub * 64 + w * 4 + du)) * 256;
#pragma unroll
            for (int kt = 0; kt < 16; ++kt) {
                bfr[kt][p][0] = pack_bf2(wr[kt * 16 + c2],     wr[kt * 16 + c2 + 1]);
                bfr[kt][p][1] = pack_bf2(wr[kt * 16 + c2 + 8], wr[kt * 16 + c2 + 9]);
            }
        }
    }
    if (tid < 16) len_sh[tid] = lengths[bb * 16 + tid];
    // zero h_shD[0] (step-0 h state)
    for (int i = tid; i < 16 * 264 / 2; i += 512)
        ((unsigned*)h_shD[0])[i] = 0u;
    __syncthreads();
    asm volatile("barrier.cluster.arrive.aligned;" ::: "memory");
    asm volatile("barrier.cluster.wait.aligned;" ::: "memory");

    int maxlen = 0;
#pragma unroll
    for (int i = 0; i < 16; i++) maxlen = max(maxlen, len_sh[i]);

    // gate mapping: thread (w, lane) -> batches r, r+8 ; unit 4w + du
    int q = lane & 3, r = lane >> 2;
    bool qe = (q & 1) == 0;
    int du = ((q & 1) << 1) | (q >> 1);
    int unit = ub * 64 + 4 * w + du;
    int len0 = len_sh[r], len1 = len_sh[r + 8];
    int gb0 = bb * 16 + r, gb1 = bb * 16 + r + 8;
    const float* xg0p = g_xg + (size_t)gb0 * T_ * 2048 + dir * 1024 + unit;
    const float* xg1p = g_xg + (size_t)gb1 * T_ * 2048 + dir * 1024 + unit;

    unsigned hsh_base = (unsigned)__cvta_generic_to_shared(&h_shD[0][0]);
    unsigned a_addr0 = hsh_base + (unsigned)(lane & 15) * 528 + ((lane >> 4) << 4);

    // push mapping: lane's peer = lane&3 (includes self via mapa-to-own-rank);
    // batches (lane>>2) and (lane>>2)+8  -> 4 ranks x 16 batches covered per warp
    int peer = lane & 3;
    unsigned dsm_peer = mapa_u32(hsh_base + (unsigned)(ub * 128 + w * 8), peer);

    float cst0 = 0.f, cst1 = 0.f;
    float xa[2][8];

    // prefetch xg for s = 0
    {
        int pos0 = dir ? (len0 - 1) : 0;
        int pos1 = dir ? (len1 - 1) : 0;
        const float* p0 = xg0p + (size_t)pos0 * 2048;
        const float* p1 = xg1p + (size_t)pos1 * 2048;
        xa[0][0] = p0[0]; xa[0][1] = p0[256]; xa[0][2] = p0[512]; xa[0][3] = p0[768];
        xa[0][4] = p1[0]; xa[0][5] = p1[256]; xa[0][6] = p1[512]; xa[0][7] = p1[768];
    }

    for (int s = 0; s < maxlen; ++s) {
        int p = s & 1;
        // ---- prefetch xg for s+1 (issues before the barrier wait) ----
        if (s + 1 < maxlen) {
            int sn = s + 1;
            if (sn < len0) {
                int pos0 = dir ? (len0 - 1 - sn) : sn;
                const float* pp = xg0p + (size_t)pos0 * 2048;
                xa[p ^ 1][0] = pp[0]; xa[p ^ 1][1] = pp[256];
                xa[p ^ 1][2] = pp[512]; xa[p ^ 1][3] = pp[768];
            }
            if (sn < len1) {
                int pos1 = dir ? (len1 - 1 - sn) : sn;
                const float* pp = xg1p + (size_t)pos1 * 2048;
                xa[p ^ 1][4] = pp[0]; xa[p ^ 1][5] = pp[256];
                xa[p ^ 1][6] = pp[512]; xa[p ^ 1][7] = pp[768];
            }
        }

        // ---- wait: peers' pushes from step s-1 into h_shD[p] landed ----
        if (s > 0)
            asm volatile("barrier.cluster.wait.aligned;" ::: "memory");

        // ---- recurrent mma, split even/odd-kt chains ----
        unsigned a_addr = a_addr0 + (unsigned)p * HBUF;
        float aA[2][4], aB[2][4];
#pragma unroll
        for (int t = 0; t < 2; ++t)
#pragma unroll
            for (int i = 0; i < 4; ++i) { aA[t][i] = 0.f; aB[t][i] = 0.f; }
#pragma unroll
        for (int kt = 0; kt < 16; kt += 2) {
            unsigned A0, A1, A2, A3;
            ldsm4(A0, A1, A2, A3, a_addr + kt * 32);
            mma_bf(aA[0][0], aA[0][1], aA[0][2], aA[0][3],
                   A0, A1, A2, A3, bfr[kt][0][0], bfr[kt][0][1]);
            mma_bf(aA[1][0], aA[1][1], aA[1][2], aA[1][3],
                   A0, A1, A2, A3, bfr[kt][1][0], bfr[kt][1][1]);
            unsigned B0, B1, B2, B3;
            ldsm4(B0, B1, B2, B3, a_addr + (kt + 1) * 32);
            mma_bf(aB[0][0], aB[0][1], aB[0][2], aB[0][3],
                   B0, B1, B2, B3, bfr[kt + 1][0][0], bfr[kt + 1][0][1]);
            mma_bf(aB[1][0], aB[1][1], aB[1][2], aB[1][3],
                   B0, B1, B2, B3, bfr[kt + 1][1][0], bfr[kt + 1][1][1]);
        }
        float acc0[4], acc1[4];
#pragma unroll
        for (int i = 0; i < 4; ++i) { acc0[i] = aA[0][i] + aB[0][i];
                                      acc1[i] = aA[1][i] + aB[1][i]; }

        // ---- lane-pair exchange: swap the "other" ntile with partner ----
        float own[4], rcv[4];
#pragma unroll
        for (int i = 0; i < 4; ++i) {
            float snd = qe ? acc1[i] : acc0[i];
            rcv[i] = __shfl_xor_sync(0xFFFFFFFFu, snd, 1);
            own[i] = qe ? acc0[i] : acc1[i];
        }
        float ai0 = (qe ? own[0] : rcv[0]) + xa[p][0];
        float af0 = (qe ? own[1] : rcv[1]) + xa[p][1];
        float ag0 = (qe ? rcv[0] : own[0]) + xa[p][2];
        float ao0 = (qe ? rcv[1] : own[1]) + xa[p][3];
        float ai1 = (qe ? own[2] : rcv[2]) + xa[p][4];
        float af1 = (qe ? own[3] : rcv[3]) + xa[p][5];
        float ag1 = (qe ? rcv[2] : own[2]) + xa[p][6];
        float ao1 = (qe ? rcv[3] : own[3]) + xa[p][7];

        bool v0 = s < len0, v1 = s < len1;
        float hv0 = 0.f, hv1 = 0.f;
        if (v0) {
            cst0 = sigm(af0) * cst0 + sigm(ai0) * tanhfast(ag0);
            hv0 = sigm(ao0) * tanhfast(cst0);
            ((__nv_bfloat16*)&h_own[w][r])[du] = __float2bfloat16(hv0);
        }
        if (v1) {
            cst1 = sigm(af1) * cst1 + sigm(ai1) * tanhfast(ag1);
            hv1 = sigm(ao1) * tanhfast(cst1);
            ((__nv_bfloat16*)&h_own[w][r + 8])[du] = __float2bfloat16(hv1);
        }
        __syncwarp();

        // ---- push own 4-unit slice to all 4 ranks (2 batches per lane) ----
        if (s + 1 < maxlen) {
            unsigned dbase = dsm_peer + (unsigned)(p ^ 1) * HBUF;
            int ba = lane >> 2;
            st_dsm64(dbase + (unsigned)ba * 528,        h_own[w][ba]);
            st_dsm64(dbase + (unsigned)(ba + 8) * 528,  h_own[w][ba + 8]);
            asm volatile("barrier.cluster.arrive.aligned;" ::: "memory");
        }

        // ---- off critical path: write layer output ----
        if (v0) {
            int pos0 = dir ? (len0 - 1 - s) : s;
            size_t xoff = ((size_t)gb0 * T_ + pos0) * E_ + dir * H_ + unit;
            if (out_fp32) g_xA[xoff] = hv0; else g_xbfB[xoff] = __float2bfloat16(hv0);
        }
        if (v1) {
            int pos1 = dir ? (len1 - 1 - s) : s;
            size_t xoff = ((size_t)gb1 * T_ + pos1) * E_ + dir * H_ + unit;
            if (out_fp32) g_xA[xoff] = hv1; else g_xbfB[xoff] = __float2bfloat16(hv1);
        }
    }

    // ---- fused tail zeroing: positions t in [len, T) get zeros ----
    for (int t = len0; t < T_; ++t) {
        size_t xoff = ((size_t)gb0 * T_ + t) * E_ + dir * H_ + unit;
        if (out_fp32) g_xA[xoff] = 0.f; else g_xbfB[xoff] = __float2bfloat16(0.f);
    }
    for (int t = len1; t < T_; ++t) {
        size_t xoff = ((size_t)gb1 * T_ + t) * E_ + dir * H_ + unit;
        if (out_fp32) g_xA[xoff] = 0.f; else g_xbfB[xoff] = __float2bfloat16(0.f);
    }

    // final barrier: cover in-flight remote ops before any CTA exits
    asm volatile("barrier.cluster.arrive.aligned;" ::: "memory");
    asm volatile("barrier.cluster.wait.aligned;" ::: "memory");
}

// ---------------- emissions -----------------------------------------------------
__global__ void k_emis(const float* __restrict__ fc_w, const float* __restrict__ fc_b) {
    int w = blockIdx.x * 8 + (threadIdx.x >> 5);
    int lane = threadIdx.x & 31;
    int j = lane < NT_ ? lane : 0;
    const float* x = g_xA + (size_t)w * E_;
    float acc = fc_b[j];
#pragma unroll 4
    for (int k = 0; k < E_; k += 4) {
        float4 xv = *(const float4*)(x + k);
        acc += xv.x * fc_w[(k + 0) * NT_ + j] + xv.y * fc_w[(k + 1) * NT_ + j]
             + xv.z * fc_w[(k + 2) * NT_ + j] + xv.w * fc_w[(k + 3) * NT_ + j];
    }
    if (lane < NT_) g_em[(size_t)w * NT_ + lane] = acc;
}

// ---------------- CRF -----------------------------------------------------------
__global__ void k_crf(const int* __restrict__ tags, const int* __restrict__ lengths,
                      const float* __restrict__ crf_start, const float* __restrict__ crf_end,
                      const float* __restrict__ crf_trans) {
    int b = blockIdx.x;
    int lane = threadIdx.x;
    int len = lengths[b];
    const int* tg = tags + b * T_;
    const float* em = g_em + (size_t)b * T_ * NT_;

    float part = 0.f;
    for (int t = lane; t < T_; t += 32) {
        if (t < len) {
            int tt = tg[t];
            part += em[t * NT_ + tt];
            if (t >= 1) part += crf_trans[tg[t - 1] * NT_ + tt];
        }
    }
#pragma unroll
    for (int o = 16; o; o >>= 1) part += __shfl_xor_sync(0xFFFFFFFFu, part, o);
    float numer = part + crf_start[tg[0]] + crf_end[tg[len - 1]];

    int j = lane < NT_ ? lane : 0;
    float etr[NT_];
#pragma unroll
    for (int i = 0; i < NT_; i++) etr[i] = expf(crf_trans[i * NT_ + j]);

    float s = crf_start[j] + em[j];
    for (int t = 1; t < len; ++t) {
        float sl = (lane < NT_) ? s : -1e30f;
        float m = sl;
#pragma unroll
        for (int o = 16; o; o >>= 1) m = fmaxf(m, __shfl_xor_sync(0xFFFFFFFFu, m, o));
        float es = expf(s - m);
        float z = 0.f;
#pragma unroll
        for (int i = 0; i < NT_; i++) {
            float ei = __shfl_sync(0xFFFFFFFFu, es, i);
            z += ei * etr[i];
        }
        s = m + logf(z) + em[t * NT_ + j];
    }
    s += crf_end[j];
    float sj = (lane < NT_) ? s : -1e30f;
    float mm = sj;
#pragma unroll
    for (int o = 16; o; o >>= 1) mm = fmaxf(mm, __shfl_xor_sync(0xFFFFFFFFu, mm, o));
    float zz = (lane < NT_) ? expf(sj - mm) : 0.f;
#pragma unroll
    for (int o = 16; o; o >>= 1) zz += __shfl_xor_sync(0xFFFFFFFFu, zz, o);
    float logZ = mm + logf(zz);
    if (lane == 0) g_llh[b] = numer - logZ;
}

// ---------------- final reduction ----------------------------------------------
__global__ void k_reduce(float* __restrict__ out) {
    int lane = threadIdx.x;
    float v = g_llh[lane];
    __shared__ float tmp[2];
#pragma unroll
    for (int o = 16; o; o >>= 1) v += __shfl_xor_sync(0xFFFFFFFFu, v, o);
    if ((lane & 31) == 0) tmp[lane >> 5] = v;
    __syncthreads();
    if (lane == 0) out[0] = -(tmp[0] + tmp[1]);
}

// ---------------- host launcher -------------------------------------------------
extern "C" void kernel_launch(void* const* d_in, const int* in_sizes, int n_in,
                              void* d_out, int out_size) {
    const int*   ids   = (const int*)d_in[0];
    const int*   lens  = (const int*)d_in[1];
    const int*   tags  = (const int*)d_in[2];
    const float* embed = (const float*)d_in[3];
    const float* w_ih  = (const float*)d_in[4];
    const float* w_hh  = (const float*)d_in[5];
    const float* b_ih  = (const float*)d_in[6];
    const float* b_hh  = (const float*)d_in[7];
    const float* fc_w  = (const float*)d_in[8];
    const float* fc_b  = (const float*)d_in[9];
    const float* c_st  = (const float*)d_in[10];
    const float* c_en  = (const float*)d_in[11];
    const float* c_tr  = (const float*)d_in[12];
    float* out = (float*)d_out;

    k_wcvt<<<2048, 256>>>(w_ih);                       // 0
    k_gather<<<B_ * T_, 128>>>(ids, embed);            // 1
    k_gemm_bf<<<dim3(16, 256), 256>>>(b_ih, b_hh, 0);  // 2
    k_lstm<<<32, 512>>>(w_hh, lens, 0, 0);             // 3
    k_gemm_bf<<<dim3(16, 256), 256>>>(b_ih, b_hh, 1);  // 4
    k_lstm<<<32, 512>>>(w_hh, lens, 1, 1);             // 5  <- profiled
    k_emis<<<B_ * T_ / 8, 256>>>(fc_w, fc_b);          // 6
    k_crf<<<B_, 32>>>(tags, lens, c_st, c_en, c_tr);   // 7
    k_reduce<<<1, 64>>>(out);                          // 8
}

// round 15
// speedup vs baseline: 1.1263x; 1.0865x over previous
#include <cuda_runtime.h>
#include <cuda_bf16.h>
#include <stdint.h>
#include <math.h>

#define B_  64
#define T_  512
#define E_  512
#define H_  256
#define NT_ 20
#define HBUF (16 * 264 * 2)   /* bytes per h buffer */

// ---------------- scratch (device globals) ------------------------------------
__device__ __nv_bfloat16 g_xbfA[B_ * T_ * E_];        // 32 MB  layer-0 input (bf16)
__device__ __nv_bfloat16 g_xbfB[B_ * T_ * E_];        // 32 MB  layer-1 input (bf16)
__device__ float g_xA[B_ * T_ * E_];                  // 64 MB  final layer output (fp32)
__device__ float g_xg[(size_t)B_ * T_ * 2048];        // 256 MB input projections
__device__ __nv_bfloat16 g_wbf[2 * 2048 * E_];        // 4 MB   w_ih in bf16
__device__ float g_em[B_ * T_ * NT_];
__device__ float g_llh[B_];

// ---------------- small helpers ------------------------------------------------
__device__ __forceinline__ unsigned pack_bf2(float a, float b) {
    __nv_bfloat162 h2 = __floats2bfloat162_rn(a, b);
    return *reinterpret_cast<unsigned*>(&h2);
}
__device__ __forceinline__ void ldsm4(unsigned& a0, unsigned& a1, unsigned& a2, unsigned& a3,
                                      unsigned addr) {
    asm volatile("ldmatrix.sync.aligned.m8n8.x4.shared.b16 {%0,%1,%2,%3}, [%4];\n"
                 : "=r"(a0), "=r"(a1), "=r"(a2), "=r"(a3) : "r"(addr));
}
__device__ __forceinline__ void mma_bf(float& d0, float& d1, float& d2, float& d3,
                                       unsigned a0, unsigned a1, unsigned a2, unsigned a3,
                                       unsigned b0, unsigned b1) {
    asm volatile("mma.sync.aligned.m16n8k16.row.col.f32.bf16.bf16.f32 "
                 "{%0,%1,%2,%3},{%4,%5,%6,%7},{%8,%9},{%0,%1,%2,%3};\n"
                 : "+f"(d0), "+f"(d1), "+f"(d2), "+f"(d3)
                 : "r"(a0), "r"(a1), "r"(a2), "r"(a3), "r"(b0), "r"(b1));
}
__device__ __forceinline__ unsigned mapa_u32(unsigned addr, int rank) {
    unsigned out;
    asm("mapa.shared::cluster.u32 %0, %1, %2;" : "=r"(out) : "r"(addr), "r"(rank));
    return out;
}
__device__ __forceinline__ void st_dsm64(unsigned addr, unsigned long long v) {
    asm volatile("st.shared::cluster.b64 [%0], %1;" :: "r"(addr), "l"(v) : "memory");
}
__device__ __forceinline__ float tanhfast(float x) {
    float y;
    asm("tanh.approx.f32 %0, %1;" : "=f"(y) : "f"(x));
    return y;
}
__device__ __forceinline__ float sigm(float x) { return 0.5f * tanhfast(0.5f * x) + 0.5f; }

// ---------------- conversion / gather ------------------------------------------
// Split into two half-grid launches so k_gemm_bf(layer 1) lands at launch
// index 5, which is where ncu's capture window sits.
__global__ void k_wcvt(const float* __restrict__ w_ih, int half) {
    int i = ((half * 1024 + blockIdx.x) * 256 + threadIdx.x) * 4;
    float4 v = *(const float4*)(w_ih + i);
    uint2 o;
    o.x = pack_bf2(v.x, v.y);
    o.y = pack_bf2(v.z, v.w);
    *(uint2*)(g_wbf + i) = o;
}

__global__ void k_gather(const int* __restrict__ ids, const float* __restrict__ embed) {
    int bt = blockIdx.x;
    int id = ids[bt];
    int e = threadIdx.x * 4;
    float4 v = *(const float4*)(embed + (size_t)id * E_ + e);
    uint2 o;
    o.x = pack_bf2(v.x, v.y);
    o.y = pack_bf2(v.z, v.w);
    *(uint2*)(g_xbfA + (size_t)bt * E_ + e) = o;
}

// ---------------- bf16 tensor-core GEMM: xg = X @ W^T + bias -------------------
__global__ void __launch_bounds__(256) k_gemm_bf(const float* __restrict__ b_ih,
                                                 const float* __restrict__ b_hh,
                                                 int layer) {
    __shared__ __align__(16) __nv_bfloat16 As[128 * 40];
    __shared__ __align__(16) __nv_bfloat16 Bs[128 * 40];

    const __nv_bfloat16* Xbf = layer ? g_xbfB : g_xbfA;
    const __nv_bfloat16* Wbf = g_wbf + (size_t)layer * 2048 * E_;
    const float* bi = b_ih + layer * 2048;
    const float* bh = b_hh + layer * 2048;

    int m0 = blockIdx.y * 128, n0 = blockIdx.x * 128;
    int tid = threadIdx.x, w = tid >> 5, lane = tid & 31;

    const __nv_bfloat16* Ag = Xbf + (size_t)(m0 + (tid >> 2)) * E_ + (tid & 3) * 8;
    const __nv_bfloat16* Bg = Wbf + (size_t)(n0 + (tid >> 2)) * E_ + (tid & 3) * 8;
    int soff = (tid >> 2) * 40 + (tid & 3) * 8;

    unsigned a_base = (unsigned)__cvta_generic_to_shared(As);
    unsigned b_base = (unsigned)__cvta_generic_to_shared(Bs);

    int mbase = (w & 1) * 64, nbase = (w >> 1) * 32;

    float acc[4][4][4];
#pragma unroll
    for (int i = 0; i < 4; i++)
#pragma unroll
        for (int j = 0; j < 4; j++)
#pragma unroll
            for (int r = 0; r < 4; r++) acc[i][j][r] = 0.f;

    uint4 ra[2], rb[2];
#pragma unroll
    for (int i = 0; i < 2; i++) {
        ra[i] = *(const uint4*)(Ag + i * 64 * E_);
        rb[i] = *(const uint4*)(Bg + i * 64 * E_);
    }

    for (int kb = 0; kb < 16; ++kb) {
#pragma unroll
        for (int i = 0; i < 2; i++) {
            *(uint4*)&As[soff + i * 64 * 40] = ra[i];
            *(uint4*)&Bs[soff + i * 64 * 40] = rb[i];
        }
        __syncthreads();
        if (kb < 15) {
#pragma unroll
            for (int i = 0; i < 2; i++) {
                ra[i] = *(const uint4*)(Ag + (kb + 1) * 32 + i * 64 * E_);
                rb[i] = *(const uint4*)(Bg + (kb + 1) * 32 + i * 64 * E_);
            }
        }
#pragma unroll
        for (int kk = 0; kk < 32; kk += 16) {
            unsigned aF[4][4], bF[4][2];
#pragma unroll
            for (int mt = 0; mt < 4; ++mt) {
                int row = mbase + mt * 16 + (lane & 15);
                int col = kk + ((lane >> 4) << 3);
                ldsm4(aF[mt][0], aF[mt][1], aF[mt][2], aF[mt][3],
                      a_base + (unsigned)(row * 40 + col) * 2);
            }
#pragma unroll
            for (int p = 0; p < 2; ++p) {
                int row = nbase + 16 * p + ((lane >> 4) << 3) + (lane & 7);
                int colb = kk + (((lane >> 3) & 1) << 3);
                ldsm4(bF[2 * p][0], bF[2 * p][1], bF[2 * p + 1][0], bF[2 * p + 1][1],
                      b_base + (unsigned)(row * 40 + colb) * 2);
            }
#pragma unroll
            for (int mt = 0; mt < 4; ++mt)
#pragma unroll
                for (int nt = 0; nt < 4; ++nt)
                    mma_bf(acc[mt][nt][0], acc[mt][nt][1], acc[mt][nt][2], acc[mt][nt][3],
                           aF[mt][0], aF[mt][1], aF[mt][2], aF[mt][3],
                           bF[nt][0], bF[nt][1]);
        }
        __syncthreads();
    }

#pragma unroll
    for (int nt = 0; nt < 4; ++nt) {
        int coln = n0 + nbase + 8 * nt + 2 * (lane & 3);
        float bb0 = bi[coln] + bh[coln];
        float bb1 = bi[coln + 1] + bh[coln + 1];
#pragma unroll
        for (int mt = 0; mt < 4; ++mt) {
            int row = m0 + mbase + 16 * mt + (lane >> 2);
            *(float2*)&g_xg[(size_t)row * 2048 + coln] =
                make_float2(acc[mt][nt][0] + bb0, acc[mt][nt][1] + bb1);
            *(float2*)&g_xg[(size_t)(row + 8) * 2048 + coln] =
                make_float2(acc[mt][nt][2] + bb0, acc[mt][nt][3] + bb1);
        }
    }
}

// ---------------- persistent BiLSTM layer (round-8 best configuration) ---------
// 64 CTAs = 8 clusters of 8.  Cluster = (dir, batch-block of 16).
// CTA rank ub owns units [ub*32, ub*32+32); warp w owns units 4w..4w+3 with
// all four gates in its mma D-fragment.  Push + cluster.sync exchange.
__global__ void __launch_bounds__(256, 1) __cluster_dims__(8, 1, 1)
k_lstm(const float* __restrict__ w_hh, const int* __restrict__ lengths,
       int layer, int out_fp32) {
    __shared__ __align__(16) __nv_bfloat16 h_shD[2][16 * 264]; // dbl-buffered full h
    __shared__ __align__(16) unsigned long long h_own[8][16];  // [warp][batch] 4 units
    __shared__ int len_sh[16];

    int cta = blockIdx.x;
    int ub  = cta & 7;          // cluster rank
    int grp = cta >> 3;
    int bb  = grp & 3;
    int dir = grp >> 2;
    int tid = threadIdx.x;
    int w = tid >> 5, lane = tid & 31;

    // ---- B fragments: warp w's 16 columns = units {4w..4w+3} x gates {0..3} ----
    unsigned bfr[16][2][2];
    {
        int c2 = (lane & 3) * 2;
#pragma unroll
        for (int p = 0; p < 2; ++p) {
            int lc = 8 * p + (lane >> 2);
            int g = lc & 3, du = lc >> 2;
            const float* wr = w_hh +
                ((size_t)((layer * 2 + dir) * 1024 + g * 256 + ub * 32 + w * 4 + du)) * 256;
#pragma unroll
            for (int kt = 0; kt < 16; ++kt) {
                bfr[kt][p][0] = pack_bf2(wr[kt * 16 + c2],     wr[kt * 16 + c2 + 1]);
                bfr[kt][p][1] = pack_bf2(wr[kt * 16 + c2 + 8], wr[kt * 16 + c2 + 9]);
            }
        }
    }
    if (tid < 16) len_sh[tid] = lengths[bb * 16 + tid];
    // zero h_shD[0] (step-0 h state)
    for (int i = tid; i < 16 * 264 / 2; i += 256)
        ((unsigned*)h_shD[0])[i] = 0u;
    __syncthreads();
    asm volatile("barrier.cluster.arrive.aligned;" ::: "memory");
    asm volatile("barrier.cluster.wait.aligned;" ::: "memory");

    int maxlen = 0;
#pragma unroll
    for (int i = 0; i < 16; i++) maxlen = max(maxlen, len_sh[i]);

    // gate mapping: thread (w, lane) -> batches r, r+8 ; unit 4w + du
    int q = lane & 3, r = lane >> 2;
    bool qe = (q & 1) == 0;
    int du = ((q & 1) << 1) | (q >> 1);
    int unit = ub * 32 + 4 * w + du;
    int len0 = len_sh[r], len1 = len_sh[r + 8];
    int gb0 = bb * 16 + r, gb1 = bb * 16 + r + 8;
    const float* xg0p = g_xg + (size_t)gb0 * T_ * 2048 + dir * 1024 + unit;
    const float* xg1p = g_xg + (size_t)gb1 * T_ * 2048 + dir * 1024 + unit;

    unsigned hsh_base = (unsigned)__cvta_generic_to_shared(&h_shD[0][0]);
    unsigned a_addr0 = hsh_base + (unsigned)(lane & 15) * 528 + ((lane >> 4) << 4);

    // push: lane's FIXED peer = lane&7; batches (lane>>3)+{0,4,8,12}
    int peer = lane & 7;
    unsigned dsm_peer = mapa_u32(hsh_base + (unsigned)((ub * 32 + 4 * w) * 2), peer);

    float cst0 = 0.f, cst1 = 0.f;
    float xa[2][8];

    // prefetch xg for s = 0
    {
        int pos0 = dir ? (len0 - 1) : 0;
        int pos1 = dir ? (len1 - 1) : 0;
        const float* p0 = xg0p + (size_t)pos0 * 2048;
        const float* p1 = xg1p + (size_t)pos1 * 2048;
        xa[0][0] = p0[0]; xa[0][1] = p0[256]; xa[0][2] = p0[512]; xa[0][3] = p0[768];
        xa[0][4] = p1[0]; xa[0][5] = p1[256]; xa[0][6] = p1[512]; xa[0][7] = p1[768];
    }

    for (int s = 0; s < maxlen; ++s) {
        int p = s & 1;
        // ---- prefetch xg for s+1 (issues before the barrier wait) ----
        if (s + 1 < maxlen) {
            int sn = s + 1;
            if (sn < len0) {
                int pos0 = dir ? (len0 - 1 - sn) : sn;
                const float* pp = xg0p + (size_t)pos0 * 2048;
                xa[p ^ 1][0] = pp[0]; xa[p ^ 1][1] = pp[256];
                xa[p ^ 1][2] = pp[512]; xa[p ^ 1][3] = pp[768];
            }
            if (sn < len1) {
                int pos1 = dir ? (len1 - 1 - sn) : sn;
                const float* pp = xg1p + (size_t)pos1 * 2048;
                xa[p ^ 1][4] = pp[0]; xa[p ^ 1][5] = pp[256];
                xa[p ^ 1][6] = pp[512]; xa[p ^ 1][7] = pp[768];
            }
        }

        // ---- wait: peers' pushes from step s-1 into h_shD[p] landed ----
        if (s > 0)
            asm volatile("barrier.cluster.wait.aligned;" ::: "memory");

        // ---- recurrent mma, split even/odd-kt chains ----
        unsigned a_addr = a_addr0 + (unsigned)p * HBUF;
        float aA[2][4], aB[2][4];
#pragma unroll
        for (int t = 0; t < 2; ++t)
#pragma unroll
            for (int i = 0; i < 4; ++i) { aA[t][i] = 0.f; aB[t][i] = 0.f; }
#pragma unroll
        for (int kt = 0; kt < 16; kt += 2) {
            unsigned A0, A1, A2, A3;
            ldsm4(A0, A1, A2, A3, a_addr + kt * 32);
            mma_bf(aA[0][0], aA[0][1], aA[0][2], aA[0][3],
                   A0, A1, A2, A3, bfr[kt][0][0], bfr[kt][0][1]);
            mma_bf(aA[1][0], aA[1][1], aA[1][2], aA[1][3],
                   A0, A1, A2, A3, bfr[kt][1][0], bfr[kt][1][1]);
            unsigned B0, B1, B2, B3;
            ldsm4(B0, B1, B2, B3, a_addr + (kt + 1) * 32);
            mma_bf(aB[0][0], aB[0][1], aB[0][2], aB[0][3],
                   B0, B1, B2, B3, bfr[kt + 1][0][0], bfr[kt + 1][0][1]);
            mma_bf(aB[1][0], aB[1][1], aB[1][2], aB[1][3],
                   B0, B1, B2, B3, bfr[kt + 1][1][0], bfr[kt + 1][1][1]);
        }
        float acc0[4], acc1[4];
#pragma unroll
        for (int i = 0; i < 4; ++i) { acc0[i] = aA[0][i] + aB[0][i];
                                      acc1[i] = aA[1][i] + aB[1][i]; }

        // ---- lane-pair exchange: swap the "other" ntile with partner ----
        float own[4], rcv[4];
#pragma unroll
        for (int i = 0; i < 4; ++i) {
            float snd = qe ? acc1[i] : acc0[i];
            rcv[i] = __shfl_xor_sync(0xFFFFFFFFu, snd, 1);
            own[i] = qe ? acc0[i] : acc1[i];
        }
        float ai0 = (qe ? own[0] : rcv[0]) + xa[p][0];
        float af0 = (qe ? own[1] : rcv[1]) + xa[p][1];
        float ag0 = (qe ? rcv[0] : own[0]) + xa[p][2];
        float ao0 = (qe ? rcv[1] : own[1]) + xa[p][3];
        float ai1 = (qe ? own[2] : rcv[2]) + xa[p][4];
        float af1 = (qe ? own[3] : rcv[3]) + xa[p][5];
        float ag1 = (qe ? rcv[2] : own[2]) + xa[p][6];
        float ao1 = (qe ? rcv[3] : own[3]) + xa[p][7];

        bool v0 = s < len0, v1 = s < len1;
        float hv0 = 0.f, hv1 = 0.f;
        if (v0) {
            cst0 = sigm(af0) * cst0 + sigm(ai0) * tanhfast(ag0);
            hv0 = sigm(ao0) * tanhfast(cst0);
            ((__nv_bfloat16*)&h_own[w][r])[du] = __float2bfloat16(hv0);
        }
        if (v1) {
            cst1 = sigm(af1) * cst1 + sigm(ai1) * tanhfast(ag1);
            hv1 = sigm(ao1) * tanhfast(cst1);
            ((__nv_bfloat16*)&h_own[w][r + 8])[du] = __float2bfloat16(hv1);
        }
        __syncwarp();

        // ---- push own 4-unit slice (all 16 batches) to fixed peer ----
        if (s + 1 < maxlen) {
            unsigned dbase = dsm_peer + (unsigned)(p ^ 1) * HBUF;
#pragma unroll
            for (int j = 0; j < 4; ++j) {
                int batch = (lane >> 3) + 4 * j;
                st_dsm64(dbase + (unsigned)batch * 528, h_own[w][batch]);
            }
            asm volatile("barrier.cluster.arrive.aligned;" ::: "memory");
        }

        // ---- off critical path: write layer output ----
        if (v0) {
            int pos0 = dir ? (len0 - 1 - s) : s;
            size_t xoff = ((size_t)gb0 * T_ + pos0) * E_ + dir * H_ + unit;
            if (out_fp32) g_xA[xoff] = hv0; else g_xbfB[xoff] = __float2bfloat16(hv0);
        }
        if (v1) {
            int pos1 = dir ? (len1 - 1 - s) : s;
            size_t xoff = ((size_t)gb1 * T_ + pos1) * E_ + dir * H_ + unit;
            if (out_fp32) g_xA[xoff] = hv1; else g_xbfB[xoff] = __float2bfloat16(hv1);
        }
    }

    // ---- fused tail zeroing: positions t in [len, T) get zeros ----
    for (int t = len0; t < T_; ++t) {
        size_t xoff = ((size_t)gb0 * T_ + t) * E_ + dir * H_ + unit;
        if (out_fp32) g_xA[xoff] = 0.f; else g_xbfB[xoff] = __float2bfloat16(0.f);
    }
    for (int t = len1; t < T_; ++t) {
        size_t xoff = ((size_t)gb1 * T_ + t) * E_ + dir * H_ + unit;
        if (out_fp32) g_xA[xoff] = 0.f; else g_xbfB[xoff] = __float2bfloat16(0.f);
    }

    // final barrier: cover in-flight remote ops before any CTA exits
    asm volatile("barrier.cluster.arrive.aligned;" ::: "memory");
    asm volatile("barrier.cluster.wait.aligned;" ::: "memory");
}

// ---------------- emissions -----------------------------------------------------
__global__ void k_emis(const float* __restrict__ fc_w, const float* __restrict__ fc_b) {
    int w = blockIdx.x * 8 + (threadIdx.x >> 5);
    int lane = threadIdx.x & 31;
    int j = lane < NT_ ? lane : 0;
    const float* x = g_xA + (size_t)w * E_;
    float acc = fc_b[j];
#pragma unroll 4
    for (int k = 0; k < E_; k += 4) {
        float4 xv = *(const float4*)(x + k);
        acc += xv.x * fc_w[(k + 0) * NT_ + j] + xv.y * fc_w[(k + 1) * NT_ + j]
             + xv.z * fc_w[(k + 2) * NT_ + j] + xv.w * fc_w[(k + 3) * NT_ + j];
    }
    if (lane < NT_) g_em[(size_t)w * NT_ + lane] = acc;
}

// ---------------- CRF -----------------------------------------------------------
__global__ void k_crf(const int* __restrict__ tags, const int* __restrict__ lengths,
                      const float* __restrict__ crf_start, const float* __restrict__ crf_end,
                      const float* __restrict__ crf_trans) {
    int b = blockIdx.x;
    int lane = threadIdx.x;
    int len = lengths[b];
    const int* tg = tags + b * T_;
    const float* em = g_em + (size_t)b * T_ * NT_;

    float part = 0.f;
    for (int t = lane; t < T_; t += 32) {
        if (t < len) {
            int tt = tg[t];
            part += em[t * NT_ + tt];
            if (t >= 1) part += crf_trans[tg[t - 1] * NT_ + tt];
        }
    }
#pragma unroll
    for (int o = 16; o; o >>= 1) part += __shfl_xor_sync(0xFFFFFFFFu, part, o);
    float numer = part + crf_start[tg[0]] + crf_end[tg[len - 1]];

    int j = lane < NT_ ? lane : 0;
    float etr[NT_];
#pragma unroll
    for (int i = 0; i < NT_; i++) etr[i] = expf(crf_trans[i * NT_ + j]);

    float s = crf_start[j] + em[j];
    for (int t = 1; t < len; ++t) {
        float sl = (lane < NT_) ? s : -1e30f;
        float m = sl;
#pragma unroll
        for (int o = 16; o; o >>= 1) m = fmaxf(m, __shfl_xor_sync(0xFFFFFFFFu, m, o));
        float es = expf(s - m);
        float z = 0.f;
#pragma unroll
        for (int i = 0; i < NT_; i++) {
            float ei = __shfl_sync(0xFFFFFFFFu, es, i);
            z += ei * etr[i];
        }
        s = m + logf(z) + em[t * NT_ + j];
    }
    s += crf_end[j];
    float sj = (lane < NT_) ? s : -1e30f;
    float mm = sj;
#pragma unroll
    for (int o = 16; o; o >>= 1) mm = fmaxf(mm, __shfl_xor_sync(0xFFFFFFFFu, mm, o));
    float zz = (lane < NT_) ? expf(sj - mm) : 0.f;
#pragma unroll
    for (int o = 16; o; o >>= 1) zz += __shfl_xor_sync(0xFFFFFFFFu, zz, o);
    float logZ = mm + logf(zz);
    if (lane == 0) g_llh[b] = numer - logZ;
}

// ---------------- final reduction ----------------------------------------------
__global__ void k_reduce(float* __restrict__ out) {
    int lane = threadIdx.x;
    float v = g_llh[lane];
    __shared__ float tmp[2];
#pragma unroll
    for (int o = 16; o; o >>= 1) v += __shfl_xor_sync(0xFFFFFFFFu, v, o);
    if ((lane & 31) == 0) tmp[lane >> 5] = v;
    __syncthreads();
    if (lane == 0) out[0] = -(tmp[0] + tmp[1]);
}

// ---------------- host launcher -------------------------------------------------
extern "C" void kernel_launch(void* const* d_in, const int* in_sizes, int n_in,
                              void* d_out, int out_size) {
    const int*   ids   = (const int*)d_in[0];
    const int*   lens  = (const int*)d_in[1];
    const int*   tags  = (const int*)d_in[2];
    const float* embed = (const float*)d_in[3];
    const float* w_ih  = (const float*)d_in[4];
    const float* w_hh  = (const float*)d_in[5];
    const float* b_ih  = (const float*)d_in[6];
    const float* b_hh  = (const float*)d_in[7];
    const float* fc_w  = (const float*)d_in[8];
    const float* fc_b  = (const float*)d_in[9];
    const float* c_st  = (const float*)d_in[10];
    const float* c_en  = (const float*)d_in[11];
    const float* c_tr  = (const float*)d_in[12];
    float* out = (float*)d_out;

    // k_wcvt split in two so k_gemm_bf(layer 1) sits at launch index 5 — the
    // slot ncu has sampled every round.  This round's profile target: the GEMM.
    k_wcvt<<<1024, 256>>>(w_ih, 0);                    // 0
    k_wcvt<<<1024, 256>>>(w_ih, 1);                    // 1
    k_gather<<<B_ * T_, 128>>>(ids, embed);            // 2
    k_gemm_bf<<<dim3(16, 256), 256>>>(b_ih, b_hh, 0);  // 3
    k_lstm<<<64, 256>>>(w_hh, lens, 0, 0);             // 4
    k_gemm_bf<<<dim3(16, 256), 256>>>(b_ih, b_hh, 1);  // 5  <- profiled
    k_lstm<<<64, 256>>>(w_hh, lens, 1, 1);             // 6
    k_emis<<<B_ * T_ / 8, 256>>>(fc_w, fc_b);          // 7
    k_crf<<<B_, 32>>>(tags, lens, c_st, c_en, c_tr);   // 8
    k_reduce<<<1, 64>>>(out);                          // 9
}